// round 9
// baseline (speedup 1.0000x reference)
#include <cuda_runtime.h>
#include <cstdint>

#define BS   2
#define SEQ  4096
#define HH   32
#define LLC  64
#define CC   (SEQ/LLC)   // 64
#define RS   72          // smem row stride in 4B words
#define GSTR (HH*64)

__device__ float g_states[(size_t)BS*CC*HH*64*64]; // [b][c][h][p][n]
__device__ float g_prefix[(size_t)BS*CC*HH*64*64];

typedef unsigned int u32;

__device__ __forceinline__ u32 cvt_tf32(float f){
    u32 u; asm("cvt.rna.tf32.f32 %0,%1;" : "=r"(u) : "f"(f)); return u;
}
__device__ __forceinline__ void mma8(float* d, const u32* a, u32 b0, u32 b1){
    asm volatile("mma.sync.aligned.m16n8k8.row.col.f32.tf32.tf32.f32 "
        "{%0,%1,%2,%3}, {%4,%5,%6,%7}, {%8,%9}, {%0,%1,%2,%3};"
        : "+f"(d[0]), "+f"(d[1]), "+f"(d[2]), "+f"(d[3])
        : "r"(a[0]), "r"(a[1]), "r"(a[2]), "r"(a[3]), "r"(b0), "r"(b1));
}

// skewed-paired layout: element (r,k) at word r*RS + W(r,k).
// pair q = 4*(k>>3)+(k&3) in [0,32) holds k (slot (k>>2)&1==0) and k+4 (slot 1);
// pair column rotated by r>>2.
__device__ __forceinline__ int Wf(int r, int k){
    return 2*(((4*(k>>3)) + (k&3) + (r>>2)) & 31) + ((k>>2)&1);
}
__device__ __forceinline__ void stp(u32* t, int r, int k, u32 v){
    t[r*RS + Wf(r,k)] = v;
}
__device__ __forceinline__ uint2 ldpair(const u32* t, int r, int kk, int qc){
    return *(const uint2*)&t[r*RS + 2*((4*kk + qc + (r>>2)) & 31)];
}
__device__ __forceinline__ void ldfragA(const u32* t, int r, int kk, int qc, u32* a){
    uint2 lo = ldpair(t, r, kk, qc), hi = ldpair(t, r+8, kk, qc);
    a[0] = lo.x; a[1] = hi.x; a[2] = lo.y; a[3] = hi.y;
}

// ===========================================================================
// K1: per (b,c,h): Y_diag -> Y, chunk states -> g_states. 128 thr, 2x2 roles.
// ===========================================================================
__global__ __launch_bounds__(128, 4) void ssd_k1(
    const float* __restrict__ X, const float* __restrict__ A,
    const float* __restrict__ Bm, const float* __restrict__ Cm,
    float* __restrict__ Y)
{
    extern __shared__ float smf[];
    u32* sXt = (u32*)smf;              // [p][s] skew; later sSt stage (plain)
    u32* sB  = (u32*)smf + 64*RS;      // [s][n] skew; later sY stage (plain)
    u32* sC  = (u32*)smf + 2*64*RS;    // [l][n] skew -> sG [l][s] -> sBt [n][l]
    float* aA   = smf + 3*64*RS;
    float* el   = aA + 64;
    float* einv = el + 64;
    float* decs = einv + 64;
    u32*   sG   = sC;
    u32*   sBt  = sC;
    float* sY   = (float*)sB;
    float* sSt  = (float*)sXt;

    const int h = blockIdx.x, c = blockIdx.y, b = blockIdx.z;
    const int tid = threadIdx.x, wid = tid >> 5, lane = tid & 31;
    const int qr = lane >> 2, qc = lane & 3;
    const int base = ((b*SEQ + c*LLC)*HH + h)*64;

    // role rotation balances SMSPs across co-resident blocks
    const int rho = (wid + h + c) & 3;
    const int rh = rho >> 1, ch = rho & 1;
    const int rA0 = rh*32, rA1 = rh*32 + 16;
    const int cB = ch*32;

    // phase 0: load tiles (tf32), X transposed into sXt
    #pragma unroll
    for (int i = tid; i < 1024; i += 128) {
        int row = i >> 4, c4 = (i & 15) << 2;
        int g = base + row*GSTR + c4;
        float4 xv = *(const float4*)&X[g];
        float4 bv = *(const float4*)&Bm[g];
        float4 cv = *(const float4*)&Cm[g];
        stp(sB, row, c4+0, cvt_tf32(bv.x)); stp(sB, row, c4+1, cvt_tf32(bv.y));
        stp(sB, row, c4+2, cvt_tf32(bv.z)); stp(sB, row, c4+3, cvt_tf32(bv.w));
        stp(sC, row, c4+0, cvt_tf32(cv.x)); stp(sC, row, c4+1, cvt_tf32(cv.y));
        stp(sC, row, c4+2, cvt_tf32(cv.z)); stp(sC, row, c4+3, cvt_tf32(cv.w));
        stp(sXt, c4+0, row, cvt_tf32(xv.x)); stp(sXt, c4+1, row, cvt_tf32(xv.y));
        stp(sXt, c4+2, row, cvt_tf32(xv.z)); stp(sXt, c4+3, row, cvt_tf32(xv.w));
    }
    if (tid < 64) aA[tid] = A[(b*SEQ + c*LLC + tid)*HH + h];
    __syncthreads();

    if (tid < 64) {
        float s = 0.f, mine = 0.f;
        #pragma unroll
        for (int j = 0; j < 64; j++) { s += aA[j]; if (j == tid) mine = s; }
        el[tid]   = __expf(mine);
        einv[tid] = __expf(-mine);
        decs[tid] = __expf(s - mine);
    }
    __syncthreads();

    // ---- mm1: G[l,s] = sum_n C[l,n]*B[s,n]; skip all-above-diag tiles ----
    const bool needA0 = (cB <= rA0 + 15);   // any kept tile in rowgroup 0
    const bool needA1 = (cB <= rA1 + 15);
    float g[2][4][4] = {};
    #pragma unroll
    for (int kk = 0; kk < 8; kk++) {
        u32 a0[4], a1[4];
        if (needA0) ldfragA(sC, rA0+qr, kk, qc, a0);
        if (needA1) ldfragA(sC, rA1+qr, kk, qc, a1);
        #pragma unroll
        for (int t = 0; t < 4; t++) {
            int c0 = cB + t*8;
            bool k0 = (c0 <= rA0 + 15), k1 = (c0 <= rA1 + 15);
            if (k0 | k1) {
                uint2 bb = ldpair(sB, c0+qr, kk, qc);
                if (k0) mma8(g[0][t], a0, bb.x, bb.y);
                if (k1) mma8(g[1][t], a1, bb.x, bb.y);
            }
        }
    }
    __syncthreads();   // mm1 reads of sC/sB done

    // mask + decay into sG (only tiles mm2 will read)
    #pragma unroll
    for (int mg = 0; mg < 2; mg++) {
        int r0 = rh*32 + mg*16;
        int l0v = r0 + qr, l1v = l0v + 8;
        float e0 = el[l0v], e1 = el[l1v];
        #pragma unroll
        for (int t = 0; t < 4; t++) {
            int c0 = cB + t*8;
            if (c0 <= r0 + 15) {
                int s0 = c0 + 2*qc, s1 = s0 + 1;
                float i0 = einv[s0], i1 = einv[s1];
                float v0 = (s0 <= l0v) ? g[mg][t][0]*e0*i0 : 0.f;
                float v1 = (s1 <= l0v) ? g[mg][t][1]*e0*i1 : 0.f;
                float v2 = (s0 <= l1v) ? g[mg][t][2]*e1*i0 : 0.f;
                float v3 = (s1 <= l1v) ? g[mg][t][3]*e1*i1 : 0.f;
                stp(sG, l0v, s0, cvt_tf32(v0)); stp(sG, l0v, s1, cvt_tf32(v1));
                stp(sG, l1v, s0, cvt_tf32(v2)); stp(sG, l1v, s1, cvt_tf32(v3));
            }
        }
    }
    __syncthreads();

    // ---- mm2: Y[l,p] = sum_s G[l,s]*X[s,p]; skip zero k-ranges ----
    float y[2][4][4] = {};
    #pragma unroll
    for (int kk = 0; kk < 8; kk++) {
        bool m0 = (8*kk <= rA0 + 15), m1 = (8*kk <= rA1 + 15);
        u32 a0[4], a1[4];
        if (m0) ldfragA(sG, rA0+qr, kk, qc, a0);
        if (m1) ldfragA(sG, rA1+qr, kk, qc, a1);
        if (m1) {
            #pragma unroll
            for (int t = 0; t < 4; t++) {
                uint2 bb = ldpair(sXt, cB + t*8 + qr, kk, qc);
                if (m0) mma8(y[0][t], a0, bb.x, bb.y);
                mma8(y[1][t], a1, bb.x, bb.y);
            }
        }
    }
    __syncthreads();   // mm2 reads of sG done

    // build sBt[n][l] = tf32( B[l][n]*dec[l] ) into sC region
    #pragma unroll
    for (int i = tid; i < 2048; i += 128) {
        int l = i >> 5, q = i & 31;
        uint2 bb = *(const uint2*)&sB[l*RS + 2*((q + (l>>2)) & 31)];
        int n_lo = 8*(q>>2) + (q&3), n_hi = n_lo + 4;
        float d = decs[l];
        stp(sBt, n_lo, l, cvt_tf32(__uint_as_float(bb.x)*d));
        stp(sBt, n_hi, l, cvt_tf32(__uint_as_float(bb.y)*d));
    }
    __syncthreads();

    // ---- mm3: S[p,n] = sum_l Xt[p,l]*(dec[l]*B[l,n]) ----
    float st[2][4][4] = {};
    #pragma unroll
    for (int kk = 0; kk < 8; kk++) {
        u32 a0[4], a1[4];
        ldfragA(sXt, rA0+qr, kk, qc, a0);
        ldfragA(sXt, rA1+qr, kk, qc, a1);
        #pragma unroll
        for (int t = 0; t < 4; t++) {
            uint2 bb = ldpair(sBt, cB + t*8 + qr, kk, qc);
            mma8(st[0][t], a0, bb.x, bb.y);
            mma8(st[1][t], a1, bb.x, bb.y);
        }
    }
    __syncthreads();   // mm3 reads of sXt/sBt done

    // stage results (plain row-major, stride RS)
    #pragma unroll
    for (int mg = 0; mg < 2; mg++) {
        int r0 = rh*32 + mg*16;
        #pragma unroll
        for (int t = 0; t < 4; t++) {
            int c0 = cB + t*8 + 2*qc;
            *(float2*)&sY[(r0+qr)*RS + c0]    = make_float2(y[mg][t][0], y[mg][t][1]);
            *(float2*)&sY[(r0+qr+8)*RS + c0]  = make_float2(y[mg][t][2], y[mg][t][3]);
            *(float2*)&sSt[(r0+qr)*RS + c0]   = make_float2(st[mg][t][0], st[mg][t][1]);
            *(float2*)&sSt[(r0+qr+8)*RS + c0] = make_float2(st[mg][t][2], st[mg][t][3]);
        }
    }
    __syncthreads();

    const int sbase = ((b*CC + c)*HH + h)*4096;
    #pragma unroll
    for (int i = tid; i < 1024; i += 128) {
        int row = i >> 4, c4 = (i & 15) << 2;
        *(float4*)&Y[base + row*GSTR + c4] = *(const float4*)&sY[row*RS + c4];
        *(float4*)&g_states[sbase + row*64 + c4] = *(const float4*)&sSt[row*RS + c4];
    }
}

// ===========================================================================
// K2: inter-chunk scan, 512 blocks (8 segments per (b,h)), prefetched
// ===========================================================================
__global__ __launch_bounds__(512) void ssd_k2(const float* __restrict__ A)
{
    __shared__ float ea[CC];
    const int blk = blockIdx.x;
    const int seg = blk & 7, bh = blk >> 3, h = bh & 31, b = bh >> 5;
    const int tid = threadIdx.x;

    if (tid < CC) {
        float s = 0.f;
        int ab = (b*SEQ + tid*LLC)*HH + h;
        for (int l = 0; l < LLC; l++) s += A[ab + l*HH];
        ea[tid] = __expf(s);
    }
    __syncthreads();

    const int e = seg*512 + tid;
    size_t off = ((size_t)(b*CC)*HH + h)*4096 + e;
    float run = 0.f;
    float v = g_states[off];
    for (int z = 0; z < CC; z++) {
        float nv = (z+1 < CC) ? g_states[off + (size_t)HH*4096] : 0.f;
        g_prefix[off] = run;
        run = run*ea[z] + v;
        v = nv;
        off += (size_t)HH*4096;
    }
}

// ===========================================================================
// K3: Y[l,p] += el[l] * sum_n C[l,n]*St[p,n]; 2x2 warp tiling.
// ===========================================================================
__global__ __launch_bounds__(128) void ssd_k3(
    const float* __restrict__ A, const float* __restrict__ Cm,
    float* __restrict__ Y)
{
    extern __shared__ float smf[];
    u32* sC = (u32*)smf;               // [l][n] skew; later sY stage (plain)
    u32* sS = (u32*)smf + 64*RS;       // [p][n] skew
    float* aA = smf + 2*64*RS;
    float* el = aA + 64;
    float* sY = (float*)sC;

    const int h = blockIdx.x, c = blockIdx.y, b = blockIdx.z;
    const int tid = threadIdx.x, wid = tid >> 5, lane = tid & 31;
    const int qr = lane >> 2, qc = lane & 3;
    const int rh = wid >> 1, ch = wid & 1;
    const int rA0 = rh*32, rA1 = rh*32 + 16;
    const int cB = ch*32;
    const int base = ((b*SEQ + c*LLC)*HH + h)*64;
    const int sbase = ((b*CC + c)*HH + h)*4096;

    #pragma unroll
    for (int i = tid; i < 1024; i += 128) {
        int row = i >> 4, c4 = (i & 15) << 2;
        float4 cv = *(const float4*)&Cm[base + row*GSTR + c4];
        float4 sv = *(const float4*)&g_prefix[sbase + row*64 + c4];
        stp(sC, row, c4+0, cvt_tf32(cv.x)); stp(sC, row, c4+1, cvt_tf32(cv.y));
        stp(sC, row, c4+2, cvt_tf32(cv.z)); stp(sC, row, c4+3, cvt_tf32(cv.w));
        stp(sS, row, c4+0, cvt_tf32(sv.x)); stp(sS, row, c4+1, cvt_tf32(sv.y));
        stp(sS, row, c4+2, cvt_tf32(sv.z)); stp(sS, row, c4+3, cvt_tf32(sv.w));
    }
    if (tid < 64) aA[tid] = A[(b*SEQ + c*LLC + tid)*HH + h];
    __syncthreads();
    if (tid < 64) {
        float s = 0.f, mine = 0.f;
        #pragma unroll
        for (int j = 0; j < 64; j++) { s += aA[j]; if (j == tid) mine = s; }
        el[tid] = __expf(mine);
    }
    __syncthreads();

    float y[2][4][4] = {};
    #pragma unroll
    for (int kk = 0; kk < 8; kk++) {
        u32 a0[4], a1[4];
        ldfragA(sC, rA0+qr, kk, qc, a0);
        ldfragA(sC, rA1+qr, kk, qc, a1);
        #pragma unroll
        for (int t = 0; t < 4; t++) {
            uint2 bb = ldpair(sS, cB + t*8 + qr, kk, qc);
            mma8(y[0][t], a0, bb.x, bb.y);
            mma8(y[1][t], a1, bb.x, bb.y);
        }
    }
    __syncthreads();   // all reads of sC done before restage

    #pragma unroll
    for (int mg = 0; mg < 2; mg++) {
        int r0 = rh*32 + mg*16;
        float e0 = el[r0+qr], e1 = el[r0+qr+8];
        #pragma unroll
        for (int t = 0; t < 4; t++) {
            int c0 = cB + t*8 + 2*qc;
            *(float2*)&sY[(r0+qr)*RS + c0]   = make_float2(e0*y[mg][t][0], e0*y[mg][t][1]);
            *(float2*)&sY[(r0+qr+8)*RS + c0] = make_float2(e1*y[mg][t][2], e1*y[mg][t][3]);
        }
    }
    __syncthreads();

    #pragma unroll
    for (int i = tid; i < 1024; i += 128) {
        int row = i >> 4, c4 = (i & 15) << 2;
        float4 o = *(float4*)&Y[base + row*GSTR + c4];
        float4 a4 = *(const float4*)&sY[row*RS + c4];
        o.x += a4.x; o.y += a4.y; o.z += a4.z; o.w += a4.w;
        *(float4*)&Y[base + row*GSTR + c4] = o;
    }
}

// ---------------------------------------------------------------------------
extern "C" void kernel_launch(void* const* d_in, const int* in_sizes, int n_in,
                              void* d_out, int out_size)
{
    const float* X  = (const float*)d_in[0];
    const float* A  = (const float*)d_in[1];
    const float* Bm = (const float*)d_in[2];
    const float* Cm = (const float*)d_in[3];
    float* Y = (float*)d_out;

    const int sm1 = (3*64*RS + 4*64) * 4;   // 56320 B -> 4 blocks/SM
    const int sm3 = (2*64*RS + 2*64) * 4;   // 37376 B -> 6 blocks/SM
    cudaFuncSetAttribute(ssd_k1, cudaFuncAttributeMaxDynamicSharedMemorySize, sm1);
    cudaFuncSetAttribute(ssd_k3, cudaFuncAttributeMaxDynamicSharedMemorySize, sm3);

    dim3 grid(HH, CC, BS);
    ssd_k1<<<grid, 128, sm1>>>(X, A, Bm, Cm, Y);
    ssd_k2<<<BS*HH*8, 512>>>(A);
    ssd_k3<<<grid, 128, sm3>>>(A, Cm, Y);
}

// round 10
// speedup vs baseline: 1.0411x; 1.0411x over previous
#include <cuda_runtime.h>
#include <cstdint>

#define BS   2
#define SEQ  4096
#define HH   32
#define LLC  64
#define CC   (SEQ/LLC)   // 64
#define RS   72          // smem row stride in 4B words
#define GSTR (HH*64)

__device__ float g_states[(size_t)BS*CC*HH*64*64]; // [b][c][h][p][n]
__device__ float g_prefix[(size_t)BS*CC*HH*64*64];

typedef unsigned int u32;

__device__ __forceinline__ u32 cvt_tf32(float f){
    u32 u; asm("cvt.rna.tf32.f32 %0,%1;" : "=r"(u) : "f"(f)); return u;
}
__device__ __forceinline__ void mma8(float* d, const u32* a, u32 b0, u32 b1){
    asm volatile("mma.sync.aligned.m16n8k8.row.col.f32.tf32.tf32.f32 "
        "{%0,%1,%2,%3}, {%4,%5,%6,%7}, {%8,%9}, {%0,%1,%2,%3};"
        : "+f"(d[0]), "+f"(d[1]), "+f"(d[2]), "+f"(d[3])
        : "r"(a[0]), "r"(a[1]), "r"(a[2]), "r"(a[3]), "r"(b0), "r"(b1));
}

// skewed-paired layout: element (r,k) at word r*RS + W(r,k).
// pair q = 4*(k>>3)+(k&3) in [0,32) holds k (slot (k>>2)&1==0) and k+4 (slot 1);
// pair column rotated by r>>2.
__device__ __forceinline__ int Wf(int r, int k){
    return 2*(((4*(k>>3)) + (k&3) + (r>>2)) & 31) + ((k>>2)&1);
}
__device__ __forceinline__ void stp(u32* t, int r, int k, u32 v){
    t[r*RS + Wf(r,k)] = v;
}
__device__ __forceinline__ uint2 ldpair(const u32* t, int r, int kk, int qc){
    return *(const uint2*)&t[r*RS + 2*((4*kk + qc + (r>>2)) & 31)];
}
__device__ __forceinline__ void ldfragA(const u32* t, int r, int kk, int qc, u32* a){
    uint2 lo = ldpair(t, r, kk, qc), hi = ldpair(t, r+8, kk, qc);
    a[0] = lo.x; a[1] = hi.x; a[2] = lo.y; a[3] = hi.y;
}

// ===========================================================================
// K1: per (b,c,h): Y_diag -> Y, chunk states -> g_states.
// 128 thr, uniform 2x2 warp tiling (warp = 32 rows x 32 cols).
// ===========================================================================
__global__ __launch_bounds__(128, 4) void ssd_k1(
    const float* __restrict__ X, const float* __restrict__ A,
    const float* __restrict__ Bm, const float* __restrict__ Cm,
    float* __restrict__ Y)
{
    extern __shared__ float smf[];
    u32* sXt = (u32*)smf;              // [p][s] skew; later sSt stage (plain)
    u32* sB  = (u32*)smf + 64*RS;      // [s][n] skew; later sY stage (plain)
    u32* sC  = (u32*)smf + 2*64*RS;    // [l][n] skew -> sG [l][s] -> sBt [n][l]
    float* aA   = smf + 3*64*RS;
    float* el   = aA + 64;
    float* einv = el + 64;
    float* decs = einv + 64;
    u32*   sG   = sC;
    u32*   sBt  = sC;
    float* sY   = (float*)sB;
    float* sSt  = (float*)sXt;

    const int h = blockIdx.x, c = blockIdx.y, b = blockIdx.z;
    const int tid = threadIdx.x, wid = tid >> 5, lane = tid & 31;
    const int qr = lane >> 2, qc = lane & 3;
    const int rh = wid >> 1, ch = wid & 1;
    const int rA0 = rh*32, rA1 = rh*32 + 16;
    const int cB = ch*32;
    const int base = ((b*SEQ + c*LLC)*HH + h)*64;

    // phase 0: load tiles (tf32), X transposed into sXt
    #pragma unroll
    for (int i = tid; i < 1024; i += 128) {
        int row = i >> 4, c4 = (i & 15) << 2;
        int g = base + row*GSTR + c4;
        float4 xv = *(const float4*)&X[g];
        float4 bv = *(const float4*)&Bm[g];
        float4 cv = *(const float4*)&Cm[g];
        stp(sB, row, c4+0, cvt_tf32(bv.x)); stp(sB, row, c4+1, cvt_tf32(bv.y));
        stp(sB, row, c4+2, cvt_tf32(bv.z)); stp(sB, row, c4+3, cvt_tf32(bv.w));
        stp(sC, row, c4+0, cvt_tf32(cv.x)); stp(sC, row, c4+1, cvt_tf32(cv.y));
        stp(sC, row, c4+2, cvt_tf32(cv.z)); stp(sC, row, c4+3, cvt_tf32(cv.w));
        stp(sXt, c4+0, row, cvt_tf32(xv.x)); stp(sXt, c4+1, row, cvt_tf32(xv.y));
        stp(sXt, c4+2, row, cvt_tf32(xv.z)); stp(sXt, c4+3, row, cvt_tf32(xv.w));
    }
    if (tid < 64) aA[tid] = A[(b*SEQ + c*LLC + tid)*HH + h];
    __syncthreads();

    if (tid < 64) {
        float s = 0.f, mine = 0.f;
        #pragma unroll
        for (int j = 0; j < 64; j++) { s += aA[j]; if (j == tid) mine = s; }
        el[tid]   = __expf(mine);
        einv[tid] = __expf(-mine);
        decs[tid] = __expf(s - mine);
    }
    __syncthreads();

    // ---- mm1: G[l,s] = sum_n C[l,n]*B[s,n]  (uniform, no skips) ----
    float g[2][4][4] = {};
    #pragma unroll
    for (int kk = 0; kk < 8; kk++) {
        u32 a0[4], a1[4];
        ldfragA(sC, rA0+qr, kk, qc, a0);
        ldfragA(sC, rA1+qr, kk, qc, a1);
        #pragma unroll
        for (int t = 0; t < 4; t++) {
            uint2 bb = ldpair(sB, cB + t*8 + qr, kk, qc);
            mma8(g[0][t], a0, bb.x, bb.y);
            mma8(g[1][t], a1, bb.x, bb.y);
        }
    }
    __syncthreads();   // mm1 reads of sC/sB done

    // mask + decay into sG (own rows)
    #pragma unroll
    for (int mg = 0; mg < 2; mg++) {
        int r0 = rh*32 + mg*16;
        int l0v = r0 + qr, l1v = l0v + 8;
        float e0 = el[l0v], e1 = el[l1v];
        #pragma unroll
        for (int t = 0; t < 4; t++) {
            int s0 = cB + t*8 + 2*qc, s1 = s0 + 1;
            float i0 = einv[s0], i1 = einv[s1];
            float v0 = (s0 <= l0v) ? g[mg][t][0]*e0*i0 : 0.f;
            float v1 = (s1 <= l0v) ? g[mg][t][1]*e0*i1 : 0.f;
            float v2 = (s0 <= l1v) ? g[mg][t][2]*e1*i0 : 0.f;
            float v3 = (s1 <= l1v) ? g[mg][t][3]*e1*i1 : 0.f;
            stp(sG, l0v, s0, cvt_tf32(v0)); stp(sG, l0v, s1, cvt_tf32(v1));
            stp(sG, l1v, s0, cvt_tf32(v2)); stp(sG, l1v, s1, cvt_tf32(v3));
        }
    }
    __syncthreads();

    // ---- mm2: Y[l,p] = sum_s G[l,s]*X[s,p]  (uniform) ----
    float y[2][4][4] = {};
    #pragma unroll
    for (int kk = 0; kk < 8; kk++) {
        u32 a0[4], a1[4];
        ldfragA(sG, rA0+qr, kk, qc, a0);
        ldfragA(sG, rA1+qr, kk, qc, a1);
        #pragma unroll
        for (int t = 0; t < 4; t++) {
            uint2 bb = ldpair(sXt, cB + t*8 + qr, kk, qc);
            mma8(y[0][t], a0, bb.x, bb.y);
            mma8(y[1][t], a1, bb.x, bb.y);
        }
    }
    __syncthreads();   // mm2 reads of sG done

    // build sBt[n][l] = tf32( B[l][n]*dec[l] ) into sC region
    #pragma unroll
    for (int i = tid; i < 2048; i += 128) {
        int l = i >> 5, q = i & 31;
        uint2 bb = *(const uint2*)&sB[l*RS + 2*((q + (l>>2)) & 31)];
        int n_lo = 8*(q>>2) + (q&3), n_hi = n_lo + 4;
        float d = decs[l];
        stp(sBt, n_lo, l, cvt_tf32(__uint_as_float(bb.x)*d));
        stp(sBt, n_hi, l, cvt_tf32(__uint_as_float(bb.y)*d));
    }
    __syncthreads();

    // ---- mm3: S[p,n] = sum_l Xt[p,l]*(dec[l]*B[l,n]) ----
    float st[2][4][4] = {};
    #pragma unroll
    for (int kk = 0; kk < 8; kk++) {
        u32 a0[4], a1[4];
        ldfragA(sXt, rA0+qr, kk, qc, a0);
        ldfragA(sXt, rA1+qr, kk, qc, a1);
        #pragma unroll
        for (int t = 0; t < 4; t++) {
            uint2 bb = ldpair(sBt, cB + t*8 + qr, kk, qc);
            mma8(st[0][t], a0, bb.x, bb.y);
            mma8(st[1][t], a1, bb.x, bb.y);
        }
    }
    __syncthreads();   // mm3 reads of sXt/sBt done

    // stage results (plain row-major, stride RS)
    #pragma unroll
    for (int mg = 0; mg < 2; mg++) {
        int r0 = rh*32 + mg*16;
        #pragma unroll
        for (int t = 0; t < 4; t++) {
            int c0 = cB + t*8 + 2*qc;
            *(float2*)&sY[(r0+qr)*RS + c0]    = make_float2(y[mg][t][0], y[mg][t][1]);
            *(float2*)&sY[(r0+qr+8)*RS + c0]  = make_float2(y[mg][t][2], y[mg][t][3]);
            *(float2*)&sSt[(r0+qr)*RS + c0]   = make_float2(st[mg][t][0], st[mg][t][1]);
            *(float2*)&sSt[(r0+qr+8)*RS + c0] = make_float2(st[mg][t][2], st[mg][t][3]);
        }
    }
    __syncthreads();

    const int sbase = ((b*CC + c)*HH + h)*4096;
    #pragma unroll
    for (int i = tid; i < 1024; i += 128) {
        int row = i >> 4, c4 = (i & 15) << 2;
        *(float4*)&Y[base + row*GSTR + c4] = *(const float4*)&sY[row*RS + c4];
        *(float4*)&g_states[sbase + row*64 + c4] = *(const float4*)&sSt[row*RS + c4];
    }
}

// ===========================================================================
// K2: inter-chunk scan, 512 blocks (8 segments per (b,h)), prefetched
// ===========================================================================
__global__ __launch_bounds__(512) void ssd_k2(const float* __restrict__ A)
{
    __shared__ float ea[CC];
    const int blk = blockIdx.x;
    const int seg = blk & 7, bh = blk >> 3, h = bh & 31, b = bh >> 5;
    const int tid = threadIdx.x;

    if (tid < CC) {
        float s = 0.f;
        int ab = (b*SEQ + tid*LLC)*HH + h;
        for (int l = 0; l < LLC; l++) s += A[ab + l*HH];
        ea[tid] = __expf(s);
    }
    __syncthreads();

    const int e = seg*512 + tid;
    size_t off = ((size_t)(b*CC)*HH + h)*4096 + e;
    float run = 0.f;
    float v = g_states[off];
    for (int z = 0; z < CC; z++) {
        float nv = (z+1 < CC) ? g_states[off + (size_t)HH*4096] : 0.f;
        g_prefix[off] = run;
        run = run*ea[z] + v;
        v = nv;
        off += (size_t)HH*4096;
    }
}

// ===========================================================================
// K3: Y[l,p] += el[l] * sum_n C[l,n]*St[p,n]; uniform 2x2 warp tiling.
// ===========================================================================
__global__ __launch_bounds__(128) void ssd_k3(
    const float* __restrict__ A, const float* __restrict__ Cm,
    float* __restrict__ Y)
{
    extern __shared__ float smf[];
    u32* sC = (u32*)smf;               // [l][n] skew; later sY stage (plain)
    u32* sS = (u32*)smf + 64*RS;       // [p][n] skew
    float* aA = smf + 2*64*RS;
    float* el = aA + 64;
    float* sY = (float*)sC;

    const int h = blockIdx.x, c = blockIdx.y, b = blockIdx.z;
    const int tid = threadIdx.x, wid = tid >> 5, lane = tid & 31;
    const int qr = lane >> 2, qc = lane & 3;
    const int rh = wid >> 1, ch = wid & 1;
    const int rA0 = rh*32, rA1 = rh*32 + 16;
    const int cB = ch*32;
    const int base = ((b*SEQ + c*LLC)*HH + h)*64;
    const int sbase = ((b*CC + c)*HH + h)*4096;

    #pragma unroll
    for (int i = tid; i < 1024; i += 128) {
        int row = i >> 4, c4 = (i & 15) << 2;
        float4 cv = *(const float4*)&Cm[base + row*GSTR + c4];
        float4 sv = *(const float4*)&g_prefix[sbase + row*64 + c4];
        stp(sC, row, c4+0, cvt_tf32(cv.x)); stp(sC, row, c4+1, cvt_tf32(cv.y));
        stp(sC, row, c4+2, cvt_tf32(cv.z)); stp(sC, row, c4+3, cvt_tf32(cv.w));
        stp(sS, row, c4+0, cvt_tf32(sv.x)); stp(sS, row, c4+1, cvt_tf32(sv.y));
        stp(sS, row, c4+2, cvt_tf32(sv.z)); stp(sS, row, c4+3, cvt_tf32(sv.w));
    }
    if (tid < 64) aA[tid] = A[(b*SEQ + c*LLC + tid)*HH + h];
    __syncthreads();
    if (tid < 64) {
        float s = 0.f, mine = 0.f;
        #pragma unroll
        for (int j = 0; j < 64; j++) { s += aA[j]; if (j == tid) mine = s; }
        el[tid] = __expf(mine);
    }
    __syncthreads();

    float y[2][4][4] = {};
    #pragma unroll
    for (int kk = 0; kk < 8; kk++) {
        u32 a0[4], a1[4];
        ldfragA(sC, rA0+qr, kk, qc, a0);
        ldfragA(sC, rA1+qr, kk, qc, a1);
        #pragma unroll
        for (int t = 0; t < 4; t++) {
            uint2 bb = ldpair(sS, cB + t*8 + qr, kk, qc);
            mma8(y[0][t], a0, bb.x, bb.y);
            mma8(y[1][t], a1, bb.x, bb.y);
        }
    }
    __syncthreads();   // all reads of sC done before restage

    #pragma unroll
    for (int mg = 0; mg < 2; mg++) {
        int r0 = rh*32 + mg*16;
        float e0 = el[r0+qr], e1 = el[r0+qr+8];
        #pragma unroll
        for (int t = 0; t < 4; t++) {
            int c0 = cB + t*8 + 2*qc;
            *(float2*)&sY[(r0+qr)*RS + c0]   = make_float2(e0*y[mg][t][0], e0*y[mg][t][1]);
            *(float2*)&sY[(r0+qr+8)*RS + c0] = make_float2(e1*y[mg][t][2], e1*y[mg][t][3]);
        }
    }
    __syncthreads();

    #pragma unroll
    for (int i = tid; i < 1024; i += 128) {
        int row = i >> 4, c4 = (i & 15) << 2;
        float4 o = *(float4*)&Y[base + row*GSTR + c4];
        float4 a4 = *(const float4*)&sY[row*RS + c4];
        o.x += a4.x; o.y += a4.y; o.z += a4.z; o.w += a4.w;
        *(float4*)&Y[base + row*GSTR + c4] = o;
    }
}

// ---------------------------------------------------------------------------
extern "C" void kernel_launch(void* const* d_in, const int* in_sizes, int n_in,
                              void* d_out, int out_size)
{
    const float* X  = (const float*)d_in[0];
    const float* A  = (const float*)d_in[1];
    const float* Bm = (const float*)d_in[2];
    const float* Cm = (const float*)d_in[3];
    float* Y = (float*)d_out;

    const int sm1 = (3*64*RS + 4*64) * 4;   // 56320 B -> 4 blocks/SM
    const int sm3 = (2*64*RS + 2*64) * 4;   // 37376 B -> 6 blocks/SM
    cudaFuncSetAttribute(ssd_k1, cudaFuncAttributeMaxDynamicSharedMemorySize, sm1);
    cudaFuncSetAttribute(ssd_k3, cudaFuncAttributeMaxDynamicSharedMemorySize, sm3);

    dim3 grid(HH, CC, BS);
    ssd_k1<<<grid, 128, sm1>>>(X, A, Bm, Cm, Y);
    ssd_k2<<<BS*HH*8, 512>>>(A);
    ssd_k3<<<grid, 128, sm3>>>(A, Cm, Y);
}

// round 11
// speedup vs baseline: 1.4507x; 1.3934x over previous
#include <cuda_runtime.h>
#include <cuda_fp16.h>
#include <cstdint>

#define BS   2
#define SEQ  4096
#define HH   32
#define LLC  64
#define CC   (SEQ/LLC)   // 64
#define RSH  40          // words per half2 table row (32 data + 8 pad)
#define GSTR (HH*64)

__device__ float g_states[(size_t)BS*CC*HH*64*64]; // [b][c][h][p][n]
__device__ float g_prefix[(size_t)BS*CC*HH*64*64];

typedef unsigned int u32;

__device__ __forceinline__ u32 f22h(float lo, float hi){
    u32 r; asm("cvt.rn.f16x2.f32 %0, %1, %2;" : "=r"(r) : "f"(hi), "f"(lo)); return r;
}
__device__ __forceinline__ float2 h22f(u32 v){
    __half2 h = *reinterpret_cast<__half2*>(&v);
    return __half22float2(h);
}
// D(16x8,f32) += A(16x16,f16 row) * B(16x8,f16 col)
__device__ __forceinline__ void mma16(float* d, const u32* a, u32 b0, u32 b1){
    asm volatile("mma.sync.aligned.m16n8k16.row.col.f32.f16.f16.f32 "
        "{%0,%1,%2,%3}, {%4,%5,%6,%7}, {%8,%9}, {%0,%1,%2,%3};"
        : "+f"(d[0]), "+f"(d[1]), "+f"(d[2]), "+f"(d[3])
        : "r"(a[0]), "r"(a[1]), "r"(a[2]), "r"(a[3]), "r"(b0), "r"(b1));
}
// skew-paired half2 layout: logical word w (halves 2w,2w+1) of row r at
// physical word r*RSH + 2*((4*(w>>3)+(w&3) + (r>>2))&15) + ((w>>2)&1)
__device__ __forceinline__ int WH(int r, int w){
    return 2*(((4*(w>>3)) + (w&3) + (r>>2)) & 15) + ((w>>2)&1);
}
__device__ __forceinline__ void stpw(u32* t, int r, int w, u32 v){
    t[r*RSH + WH(r,w)] = v;
}
// LDS.64 of logical words (8kk+qc, 8kk+qc+4) from row r
__device__ __forceinline__ uint2 ldpairH(const u32* t, int r, int kk, int qc){
    return *(const uint2*)&t[r*RSH + 2*((4*kk + qc + (r>>2)) & 15)];
}
__device__ __forceinline__ void ldfragH(const u32* t, int r, int kk, int qc, u32* a){
    uint2 lo = ldpairH(t, r, kk, qc), hi = ldpairH(t, r+8, kk, qc);
    a[0] = lo.x; a[1] = hi.x; a[2] = lo.y; a[3] = hi.y;
}

// ===========================================================================
// K1: per (b,c,h): Y_diag -> Y, chunk states -> g_states. fp16 MMA, 4 warps.
// ===========================================================================
__global__ __launch_bounds__(128, 4) void ssd_k1(
    const float* __restrict__ X, const float* __restrict__ A,
    const float* __restrict__ Bm, const float* __restrict__ Cm,
    float* __restrict__ Y)
{
    extern __shared__ u32 smw[];
    u32* sXt = smw;                 // [p][s-halves]
    u32* sB  = smw + 64*RSH;        // [s][n-halves]
    u32* sC  = smw + 2*64*RSH;      // [l][n-halves] -> sG [l][s-halves]
    u32* sBt = smw + 3*64*RSH;      // [n][l-halves], dec folded
    float* aA   = (float*)(smw + 4*64*RSH);
    float* el   = aA + 64;
    float* einv = el + 64;
    float* decs = einv + 64;
    u32*   sG   = sC;

    const int h = blockIdx.x, c = blockIdx.y, b = blockIdx.z;
    const int tid = threadIdx.x, wid = tid >> 5, lane = tid & 31;
    const int qr = lane >> 2, qc = lane & 3;
    const int rh = wid >> 1, ch = wid & 1;
    const int rA0 = rh*32, rA1 = rh*32 + 16;
    const int cB = ch*32;
    const int base = ((b*SEQ + c*LLC)*HH + h)*64;

    // phase A: load B, C as half2 (paired layout); aA
    #pragma unroll
    for (int i = tid; i < 1024; i += 128) {
        int row = i >> 4, c4 = (i & 15) << 2;
        int g = base + row*GSTR + c4;
        float4 bv = *(const float4*)&Bm[g];
        float4 cv = *(const float4*)&Cm[g];
        stpw(sB, row, c4>>1,     f22h(bv.x, bv.y));
        stpw(sB, row, (c4>>1)+1, f22h(bv.z, bv.w));
        stpw(sC, row, c4>>1,     f22h(cv.x, cv.y));
        stpw(sC, row, (c4>>1)+1, f22h(cv.z, cv.w));
    }
    if (tid < 64) aA[tid] = A[(b*SEQ + c*LLC + tid)*HH + h];

    // phase C: X transposed straight from global into sXt[p][s-halves]
    #pragma unroll
    for (int m = 0; m < 8; m++) {
        int w = wid*8 + m;                        // s-pair
        const float2 x0 = *(const float2*)&X[base + (2*w)*GSTR + 2*lane];
        const float2 x1 = *(const float2*)&X[base + (2*w+1)*GSTR + 2*lane];
        stpw(sXt, 2*lane,   w, f22h(x0.x, x1.x));
        stpw(sXt, 2*lane+1, w, f22h(x0.y, x1.y));
    }
    __syncthreads();

    if (tid < 64) {
        float s = 0.f, mine = 0.f;
        #pragma unroll
        for (int j = 0; j < 64; j++) { s += aA[j]; if (j == tid) mine = s; }
        el[tid]   = __expf(mine);
        einv[tid] = __expf(-mine);
        decs[tid] = __expf(s - mine);
    }
    __syncthreads();

    // phase D: sBt[n][l-halves] = dec[l]*B[l][n]
    #pragma unroll
    for (int m = 0; m < 8; m++) {
        int w = wid*8 + m;                        // l-pair
        float d0 = decs[2*w], d1 = decs[2*w+1];
        u32 v0 = sB[(2*w)*RSH   + WH(2*w,   lane)];
        u32 v1 = sB[(2*w+1)*RSH + WH(2*w+1, lane)];
        float2 fa = h22f(v0), fb = h22f(v1);
        stpw(sBt, 2*lane,   w, f22h(fa.x*d0, fb.x*d1));
        stpw(sBt, 2*lane+1, w, f22h(fa.y*d0, fb.y*d1));
    }

    // ---- mm1: G[l,s] = sum_n C[l,n]*B[s,n] ----
    float g[2][4][4] = {};
    #pragma unroll
    for (int kk = 0; kk < 4; kk++) {
        u32 a0[4], a1[4];
        ldfragH(sC, rA0+qr, kk, qc, a0);
        ldfragH(sC, rA1+qr, kk, qc, a1);
        #pragma unroll
        for (int t = 0; t < 4; t++) {
            uint2 bb = ldpairH(sB, cB + t*8 + qr, kk, qc);
            mma16(g[0][t], a0, bb.x, bb.y);
            mma16(g[1][t], a1, bb.x, bb.y);
        }
    }
    __syncthreads();   // mm1 reads of sC/sB done everywhere (covers phase D too)

    // mask + decay into sG[l][s-halves]
    #pragma unroll
    for (int mg = 0; mg < 2; mg++) {
        int r0 = rh*32 + mg*16;
        int l0v = r0 + qr, l1v = l0v + 8;
        float e0 = el[l0v], e1 = el[l1v];
        #pragma unroll
        for (int t = 0; t < 4; t++) {
            int s0 = cB + t*8 + 2*qc, s1 = s0 + 1;
            int w  = ((cB + t*8) >> 1) + qc;
            float i0 = einv[s0], i1 = einv[s1];
            float v0 = (s0 <= l0v) ? g[mg][t][0]*e0*i0 : 0.f;
            float v1 = (s1 <= l0v) ? g[mg][t][1]*e0*i1 : 0.f;
            float v2 = (s0 <= l1v) ? g[mg][t][2]*e1*i0 : 0.f;
            float v3 = (s1 <= l1v) ? g[mg][t][3]*e1*i1 : 0.f;
            stpw(sG, l0v, w, f22h(v0, v1));
            stpw(sG, l1v, w, f22h(v2, v3));
        }
    }
    __syncthreads();

    // ---- mm2: Y[l,p] = sum_s G[l,s]*X[s,p] ----
    float y[2][4][4] = {};
    #pragma unroll
    for (int kk = 0; kk < 4; kk++) {
        u32 a0[4], a1[4];
        ldfragH(sG, rA0+qr, kk, qc, a0);
        ldfragH(sG, rA1+qr, kk, qc, a1);
        #pragma unroll
        for (int t = 0; t < 4; t++) {
            uint2 bb = ldpairH(sXt, cB + t*8 + qr, kk, qc);
            mma16(y[0][t], a0, bb.x, bb.y);
            mma16(y[1][t], a1, bb.x, bb.y);
        }
    }

    // ---- mm3: S[p,n] = sum_l Xt[p,l]*(dec[l]*B[l,n]) ----
    float st[2][4][4] = {};
    #pragma unroll
    for (int kk = 0; kk < 4; kk++) {
        u32 a0[4], a1[4];
        ldfragH(sXt, rA0+qr, kk, qc, a0);
        ldfragH(sXt, rA1+qr, kk, qc, a1);
        #pragma unroll
        for (int t = 0; t < 4; t++) {
            uint2 bb = ldpairH(sBt, cB + t*8 + qr, kk, qc);
            mma16(st[0][t], a0, bb.x, bb.y);
            mma16(st[1][t], a1, bb.x, bb.y);
        }
    }

    // direct global stores (each float2 from 4 lanes fills a full 32B sector)
    const int sbase = ((b*CC + c)*HH + h)*4096;
    #pragma unroll
    for (int mg = 0; mg < 2; mg++) {
        int r0 = rh*32 + mg*16;
        int row0 = r0 + qr, row1 = r0 + qr + 8;
        #pragma unroll
        for (int t = 0; t < 4; t++) {
            int c0 = cB + t*8 + 2*qc;
            *(float2*)&Y[base + row0*GSTR + c0] = make_float2(y[mg][t][0], y[mg][t][1]);
            *(float2*)&Y[base + row1*GSTR + c0] = make_float2(y[mg][t][2], y[mg][t][3]);
            *(float2*)&g_states[sbase + row0*64 + c0] = make_float2(st[mg][t][0], st[mg][t][1]);
            *(float2*)&g_states[sbase + row1*64 + c0] = make_float2(st[mg][t][2], st[mg][t][3]);
        }
    }
}

// ===========================================================================
// K2: inter-chunk scan, 512 blocks (8 segments per (b,h)), prefetched
// ===========================================================================
__global__ __launch_bounds__(512) void ssd_k2(const float* __restrict__ A)
{
    __shared__ float ea[CC];
    const int blk = blockIdx.x;
    const int seg = blk & 7, bh = blk >> 3, h = bh & 31, b = bh >> 5;
    const int tid = threadIdx.x;

    if (tid < CC) {
        float s = 0.f;
        int ab = (b*SEQ + tid*LLC)*HH + h;
        for (int l = 0; l < LLC; l++) s += A[ab + l*HH];
        ea[tid] = __expf(s);
    }
    __syncthreads();

    const int e = seg*512 + tid;
    size_t off = ((size_t)(b*CC)*HH + h)*4096 + e;
    float run = 0.f;
    float v = g_states[off];
    for (int z = 0; z < CC; z++) {
        float nv = (z+1 < CC) ? g_states[off + (size_t)HH*4096] : 0.f;
        g_prefix[off] = run;
        run = run*ea[z] + v;
        v = nv;
        off += (size_t)HH*4096;
    }
}

// ===========================================================================
// K3: Y[l,p] += el[l] * sum_n C[l,n]*St[p,n]; fp16 MMA, direct Y RMW.
// ===========================================================================
__global__ __launch_bounds__(128) void ssd_k3(
    const float* __restrict__ A, const float* __restrict__ Cm,
    float* __restrict__ Y)
{
    extern __shared__ u32 smw[];
    u32* sC = smw;                 // [l][n-halves]
    u32* sS = smw + 64*RSH;        // [p][n-halves]
    float* aA = (float*)(smw + 2*64*RSH);
    float* el = aA + 64;

    const int h = blockIdx.x, c = blockIdx.y, b = blockIdx.z;
    const int tid = threadIdx.x, wid = tid >> 5, lane = tid & 31;
    const int qr = lane >> 2, qc = lane & 3;
    const int rh = wid >> 1, ch = wid & 1;
    const int rA0 = rh*32, rA1 = rh*32 + 16;
    const int cB = ch*32;
    const int base = ((b*SEQ + c*LLC)*HH + h)*64;
    const int sbase = ((b*CC + c)*HH + h)*4096;

    #pragma unroll
    for (int i = tid; i < 1024; i += 128) {
        int row = i >> 4, c4 = (i & 15) << 2;
        float4 cv = *(const float4*)&Cm[base + row*GSTR + c4];
        float4 sv = *(const float4*)&g_prefix[sbase + row*64 + c4];
        stpw(sC, row, c4>>1,     f22h(cv.x, cv.y));
        stpw(sC, row, (c4>>1)+1, f22h(cv.z, cv.w));
        stpw(sS, row, c4>>1,     f22h(sv.x, sv.y));
        stpw(sS, row, (c4>>1)+1, f22h(sv.z, sv.w));
    }
    if (tid < 64) aA[tid] = A[(b*SEQ + c*LLC + tid)*HH + h];
    __syncthreads();
    if (tid < 64) {
        float s = 0.f, mine = 0.f;
        #pragma unroll
        for (int j = 0; j < 64; j++) { s += aA[j]; if (j == tid) mine = s; }
        el[tid] = __expf(mine);
    }
    __syncthreads();

    float y[2][4][4] = {};
    #pragma unroll
    for (int kk = 0; kk < 4; kk++) {
        u32 a0[4], a1[4];
        ldfragH(sC, rA0+qr, kk, qc, a0);
        ldfragH(sC, rA1+qr, kk, qc, a1);
        #pragma unroll
        for (int t = 0; t < 4; t++) {
            uint2 bb = ldpairH(sS, cB + t*8 + qr, kk, qc);
            mma16(y[0][t], a0, bb.x, bb.y);
            mma16(y[1][t], a1, bb.x, bb.y);
        }
    }

    // direct read-modify-write on Y
    #pragma unroll
    for (int mg = 0; mg < 2; mg++) {
        int r0 = rh*32 + mg*16;
        int row0 = r0 + qr, row1 = r0 + qr + 8;
        float e0 = el[row0], e1 = el[row1];
        #pragma unroll
        for (int t = 0; t < 4; t++) {
            int c0 = cB + t*8 + 2*qc;
            float2 o0 = *(float2*)&Y[base + row0*GSTR + c0];
            float2 o1 = *(float2*)&Y[base + row1*GSTR + c0];
            o0.x += e0*y[mg][t][0]; o0.y += e0*y[mg][t][1];
            o1.x += e1*y[mg][t][2]; o1.y += e1*y[mg][t][3];
            *(float2*)&Y[base + row0*GSTR + c0] = o0;
            *(float2*)&Y[base + row1*GSTR + c0] = o1;
        }
    }
}

// ---------------------------------------------------------------------------
extern "C" void kernel_launch(void* const* d_in, const int* in_sizes, int n_in,
                              void* d_out, int out_size)
{
    const float* X  = (const float*)d_in[0];
    const float* A  = (const float*)d_in[1];
    const float* Bm = (const float*)d_in[2];
    const float* Cm = (const float*)d_in[3];
    float* Y = (float*)d_out;

    const int sm1 = (4*64*RSH + 4*64) * 4;   // 41984 B -> 4+ blocks/SM
    const int sm3 = (2*64*RSH + 2*64) * 4;   // 20992 B
    cudaFuncSetAttribute(ssd_k1, cudaFuncAttributeMaxDynamicSharedMemorySize, sm1);
    cudaFuncSetAttribute(ssd_k3, cudaFuncAttributeMaxDynamicSharedMemorySize, sm3);

    dim3 grid(HH, CC, BS);
    ssd_k1<<<grid, 128, sm1>>>(X, A, Bm, Cm, Y);
    ssd_k2<<<BS*HH*8, 512>>>(A);
    ssd_k3<<<grid, 128, sm3>>>(A, Cm, Y);
}

// round 12
// speedup vs baseline: 1.6361x; 1.1279x over previous
#include <cuda_runtime.h>
#include <cuda_fp16.h>
#include <cstdint>

#define BS   2
#define SEQ  4096
#define HH   32
#define LLC  64
#define CC   (SEQ/LLC)   // 64
#define RSH  40          // words per half2 table row (32 data + 8 pad)
#define GSTR (HH*64)

__device__ __half g_states[(size_t)BS*CC*HH*64*64];  // [b][c][h][p][n] fp16
__device__ __half g_prefix[(size_t)BS*CC*HH*64*64];  // [b][c][h][p][n] fp16
__device__ __half g_ydiag [(size_t)BS*SEQ*HH*64];    // [b][s][h][p]    fp16

typedef unsigned int u32;

__device__ __forceinline__ u32 f22h(float lo, float hi){
    u32 r; asm("cvt.rn.f16x2.f32 %0, %1, %2;" : "=r"(r) : "f"(hi), "f"(lo)); return r;
}
__device__ __forceinline__ float2 h22f(u32 v){
    __half2 h = *reinterpret_cast<__half2*>(&v);
    return __half22float2(h);
}
// D(16x8,f32) += A(16x16,f16 row) * B(16x8,f16 col)
__device__ __forceinline__ void mma16(float* d, const u32* a, u32 b0, u32 b1){
    asm volatile("mma.sync.aligned.m16n8k16.row.col.f32.f16.f16.f32 "
        "{%0,%1,%2,%3}, {%4,%5,%6,%7}, {%8,%9}, {%0,%1,%2,%3};"
        : "+f"(d[0]), "+f"(d[1]), "+f"(d[2]), "+f"(d[3])
        : "r"(a[0]), "r"(a[1]), "r"(a[2]), "r"(a[3]), "r"(b0), "r"(b1));
}
// skew-paired half2 layout: logical word w (halves 2w,2w+1) of row r at
// physical word r*RSH + 2*((4*(w>>3)+(w&3) + (r>>2))&15) + ((w>>2)&1)
__device__ __forceinline__ int WH(int r, int w){
    return 2*(((4*(w>>3)) + (w&3) + (r>>2)) & 15) + ((w>>2)&1);
}
__device__ __forceinline__ void stpw(u32* t, int r, int w, u32 v){
    t[r*RSH + WH(r,w)] = v;
}
__device__ __forceinline__ uint2 ldpairH(const u32* t, int r, int kk, int qc){
    return *(const uint2*)&t[r*RSH + 2*((4*kk + qc + (r>>2)) & 15)];
}
__device__ __forceinline__ void ldfragH(const u32* t, int r, int kk, int qc, u32* a){
    uint2 lo = ldpairH(t, r, kk, qc), hi = ldpairH(t, r+8, kk, qc);
    a[0] = lo.x; a[1] = hi.x; a[2] = lo.y; a[3] = hi.y;
}

// ===========================================================================
// K1: per (b,c,h): Y_diag (fp16) -> g_ydiag, chunk states (fp16) -> g_states
// ===========================================================================
__global__ __launch_bounds__(128, 4) void ssd_k1(
    const float* __restrict__ X, const float* __restrict__ A,
    const float* __restrict__ Bm, const float* __restrict__ Cm)
{
    extern __shared__ u32 smw[];
    u32* sXt = smw;                 // [p][s-halves]
    u32* sB  = smw + 64*RSH;        // [s][n-halves]
    u32* sC  = smw + 2*64*RSH;      // [l][n-halves] -> sG [l][s-halves]
    u32* sBt = smw + 3*64*RSH;      // [n][l-halves], dec folded
    float* aA   = (float*)(smw + 4*64*RSH);
    float* el   = aA + 64;
    float* einv = el + 64;
    float* decs = einv + 64;
    u32*   sG   = sC;

    const int h = blockIdx.x, c = blockIdx.y, b = blockIdx.z;
    const int tid = threadIdx.x, wid = tid >> 5, lane = tid & 31;
    const int qr = lane >> 2, qc = lane & 3;
    const int rh = wid >> 1, ch = wid & 1;
    const int rA0 = rh*32, rA1 = rh*32 + 16;
    const int cB = ch*32;
    const int base = ((b*SEQ + c*LLC)*HH + h)*64;

    // phase A: load B, C as half2 (paired layout); aA
    #pragma unroll
    for (int i = tid; i < 1024; i += 128) {
        int row = i >> 4, c4 = (i & 15) << 2;
        int g = base + row*GSTR + c4;
        float4 bv = *(const float4*)&Bm[g];
        float4 cv = *(const float4*)&Cm[g];
        stpw(sB, row, c4>>1,     f22h(bv.x, bv.y));
        stpw(sB, row, (c4>>1)+1, f22h(bv.z, bv.w));
        stpw(sC, row, c4>>1,     f22h(cv.x, cv.y));
        stpw(sC, row, (c4>>1)+1, f22h(cv.z, cv.w));
    }
    if (tid < 64) aA[tid] = A[(b*SEQ + c*LLC + tid)*HH + h];

    // phase C: X transposed straight from global into sXt[p][s-halves]
    #pragma unroll
    for (int m = 0; m < 8; m++) {
        int w = wid*8 + m;                        // s-pair
        const float2 x0 = *(const float2*)&X[base + (2*w)*GSTR + 2*lane];
        const float2 x1 = *(const float2*)&X[base + (2*w+1)*GSTR + 2*lane];
        stpw(sXt, 2*lane,   w, f22h(x0.x, x1.x));
        stpw(sXt, 2*lane+1, w, f22h(x0.y, x1.y));
    }
    __syncthreads();

    if (tid < 64) {
        float s = 0.f, mine = 0.f;
        #pragma unroll
        for (int j = 0; j < 64; j++) { s += aA[j]; if (j == tid) mine = s; }
        el[tid]   = __expf(mine);
        einv[tid] = __expf(-mine);
        decs[tid] = __expf(s - mine);
    }
    __syncthreads();

    // phase D: sBt[n][l-halves] = dec[l]*B[l][n]
    #pragma unroll
    for (int m = 0; m < 8; m++) {
        int w = wid*8 + m;                        // l-pair
        float d0 = decs[2*w], d1 = decs[2*w+1];
        u32 v0 = sB[(2*w)*RSH   + WH(2*w,   lane)];
        u32 v1 = sB[(2*w+1)*RSH + WH(2*w+1, lane)];
        float2 fa = h22f(v0), fb = h22f(v1);
        stpw(sBt, 2*lane,   w, f22h(fa.x*d0, fb.x*d1));
        stpw(sBt, 2*lane+1, w, f22h(fa.y*d0, fb.y*d1));
    }

    // ---- mm1: G[l,s] = sum_n C[l,n]*B[s,n] ----
    float g[2][4][4] = {};
    #pragma unroll
    for (int kk = 0; kk < 4; kk++) {
        u32 a0[4], a1[4];
        ldfragH(sC, rA0+qr, kk, qc, a0);
        ldfragH(sC, rA1+qr, kk, qc, a1);
        #pragma unroll
        for (int t = 0; t < 4; t++) {
            uint2 bb = ldpairH(sB, cB + t*8 + qr, kk, qc);
            mma16(g[0][t], a0, bb.x, bb.y);
            mma16(g[1][t], a1, bb.x, bb.y);
        }
    }
    __syncthreads();   // mm1 reads of sC/sB done (covers phase D too)

    // mask + decay into sG[l][s-halves]
    #pragma unroll
    for (int mg = 0; mg < 2; mg++) {
        int r0 = rh*32 + mg*16;
        int l0v = r0 + qr, l1v = l0v + 8;
        float e0 = el[l0v], e1 = el[l1v];
        #pragma unroll
        for (int t = 0; t < 4; t++) {
            int s0 = cB + t*8 + 2*qc, s1 = s0 + 1;
            int w  = ((cB + t*8) >> 1) + qc;
            float i0 = einv[s0], i1 = einv[s1];
            float v0 = (s0 <= l0v) ? g[mg][t][0]*e0*i0 : 0.f;
            float v1 = (s1 <= l0v) ? g[mg][t][1]*e0*i1 : 0.f;
            float v2 = (s0 <= l1v) ? g[mg][t][2]*e1*i0 : 0.f;
            float v3 = (s1 <= l1v) ? g[mg][t][3]*e1*i1 : 0.f;
            stpw(sG, l0v, w, f22h(v0, v1));
            stpw(sG, l1v, w, f22h(v2, v3));
        }
    }
    __syncthreads();

    // ---- mm2: Y[l,p] = sum_s G[l,s]*X[s,p] ----
    float y[2][4][4] = {};
    #pragma unroll
    for (int kk = 0; kk < 4; kk++) {
        u32 a0[4], a1[4];
        ldfragH(sG, rA0+qr, kk, qc, a0);
        ldfragH(sG, rA1+qr, kk, qc, a1);
        #pragma unroll
        for (int t = 0; t < 4; t++) {
            uint2 bb = ldpairH(sXt, cB + t*8 + qr, kk, qc);
            mma16(y[0][t], a0, bb.x, bb.y);
            mma16(y[1][t], a1, bb.x, bb.y);
        }
    }

    // ---- mm3: S[p,n] = sum_l Xt[p,l]*(dec[l]*B[l,n]) ----
    float st[2][4][4] = {};
    #pragma unroll
    for (int kk = 0; kk < 4; kk++) {
        u32 a0[4], a1[4];
        ldfragH(sXt, rA0+qr, kk, qc, a0);
        ldfragH(sXt, rA1+qr, kk, qc, a1);
        #pragma unroll
        for (int t = 0; t < 4; t++) {
            uint2 bb = ldpairH(sBt, cB + t*8 + qr, kk, qc);
            mma16(st[0][t], a0, bb.x, bb.y);
            mma16(st[1][t], a1, bb.x, bb.y);
        }
    }

    // fp16 packed stores (adjacent t-tiles fill full 32B sectors in L2)
    const int sbase = ((b*CC + c)*HH + h)*4096;
    #pragma unroll
    for (int mg = 0; mg < 2; mg++) {
        int r0 = rh*32 + mg*16;
        int row0 = r0 + qr, row1 = r0 + qr + 8;
        #pragma unroll
        for (int t = 0; t < 4; t++) {
            int c0 = cB + t*8 + 2*qc;
            *(u32*)&g_ydiag[base + row0*GSTR + c0] = f22h(y[mg][t][0], y[mg][t][1]);
            *(u32*)&g_ydiag[base + row1*GSTR + c0] = f22h(y[mg][t][2], y[mg][t][3]);
            *(u32*)&g_states[sbase + row0*64 + c0] = f22h(st[mg][t][0], st[mg][t][1]);
            *(u32*)&g_states[sbase + row1*64 + c0] = f22h(st[mg][t][2], st[mg][t][3]);
        }
    }
}

// ===========================================================================
// K2: inter-chunk scan over fp16 words; fp32 accumulation in registers.
// 256 blocks (4 segments per (b,h)) x 512 threads; prefetched.
// ===========================================================================
__global__ __launch_bounds__(512) void ssd_k2(const float* __restrict__ A)
{
    __shared__ float ea[CC];
    const int blk = blockIdx.x;
    const int seg = blk & 3, bh = blk >> 2, h = bh & 31, b = bh >> 5;
    const int tid = threadIdx.x;

    if (tid < CC) {
        float s = 0.f;
        int ab = (b*SEQ + tid*LLC)*HH + h;
        for (int l = 0; l < LLC; l++) s += A[ab + l*HH];
        ea[tid] = __expf(s);
    }
    __syncthreads();

    const u32* sp = (const u32*)g_states;
    u32* pp = (u32*)g_prefix;
    const int w = seg*512 + tid;                    // word in [0,2048)
    size_t off = ((size_t)(b*CC)*HH + h)*2048 + w;
    float r0 = 0.f, r1 = 0.f;
    u32 v = sp[off];
    for (int z = 0; z < CC; z++) {
        u32 nv = (z+1 < CC) ? sp[off + (size_t)HH*2048] : 0u;
        pp[off] = f22h(r0, r1);
        float2 f = h22f(v);
        float e = ea[z];
        r0 = r0*e + f.x; r1 = r1*e + f.y;
        v = nv;
        off += (size_t)HH*2048;
    }
}

// ===========================================================================
// K3: Y[l,p] = ydiag[l,p] + el[l] * sum_n C[l,n]*St[p,n]  (single fp32 write)
// ===========================================================================
__global__ __launch_bounds__(128) void ssd_k3(
    const float* __restrict__ A, const float* __restrict__ Cm,
    float* __restrict__ Y)
{
    extern __shared__ u32 smw[];
    u32* sC = smw;                 // [l][n-halves]
    u32* sS = smw + 64*RSH;        // [p][n-halves]
    float* aA = (float*)(smw + 2*64*RSH);
    float* el = aA + 64;

    const int h = blockIdx.x, c = blockIdx.y, b = blockIdx.z;
    const int tid = threadIdx.x, wid = tid >> 5, lane = tid & 31;
    const int qr = lane >> 2, qc = lane & 3;
    const int rh = wid >> 1, ch = wid & 1;
    const int rA0 = rh*32, rA1 = rh*32 + 16;
    const int cB = ch*32;
    const int base = ((b*SEQ + c*LLC)*HH + h)*64;
    const int sbase = ((b*CC + c)*HH + h)*4096;

    // C: fp32->fp16 convert; prefix: already half2 words, direct restage
    #pragma unroll
    for (int i = tid; i < 1024; i += 128) {
        int row = i >> 4, c4 = (i & 15) << 2;
        float4 cv = *(const float4*)&Cm[base + row*GSTR + c4];
        stpw(sC, row, c4>>1,     f22h(cv.x, cv.y));
        stpw(sC, row, (c4>>1)+1, f22h(cv.z, cv.w));
        uint2 sv = *(const uint2*)&g_prefix[sbase + row*64 + c4];
        stpw(sS, row, c4>>1,     sv.x);
        stpw(sS, row, (c4>>1)+1, sv.y);
    }
    if (tid < 64) aA[tid] = A[(b*SEQ + c*LLC + tid)*HH + h];
    __syncthreads();
    if (tid < 64) {
        float s = 0.f, mine = 0.f;
        #pragma unroll
        for (int j = 0; j < 64; j++) { s += aA[j]; if (j == tid) mine = s; }
        el[tid] = __expf(mine);
    }
    __syncthreads();

    float y[2][4][4] = {};
    #pragma unroll
    for (int kk = 0; kk < 4; kk++) {
        u32 a0[4], a1[4];
        ldfragH(sC, rA0+qr, kk, qc, a0);
        ldfragH(sC, rA1+qr, kk, qc, a1);
        #pragma unroll
        for (int t = 0; t < 4; t++) {
            uint2 bb = ldpairH(sS, cB + t*8 + qr, kk, qc);
            mma16(y[0][t], a0, bb.x, bb.y);
            mma16(y[1][t], a1, bb.x, bb.y);
        }
    }

    // Y = ydiag + el * acc   (read fp16 stash, single fp32 write)
    #pragma unroll
    for (int mg = 0; mg < 2; mg++) {
        int r0 = rh*32 + mg*16;
        int row0 = r0 + qr, row1 = r0 + qr + 8;
        float e0 = el[row0], e1 = el[row1];
        #pragma unroll
        for (int t = 0; t < 4; t++) {
            int c0 = cB + t*8 + 2*qc;
            float2 d0 = h22f(*(const u32*)&g_ydiag[base + row0*GSTR + c0]);
            float2 d1 = h22f(*(const u32*)&g_ydiag[base + row1*GSTR + c0]);
            *(float2*)&Y[base + row0*GSTR + c0] =
                make_float2(d0.x + e0*y[mg][t][0], d0.y + e0*y[mg][t][1]);
            *(float2*)&Y[base + row1*GSTR + c0] =
                make_float2(d1.x + e1*y[mg][t][2], d1.y + e1*y[mg][t][3]);
        }
    }
}

// ---------------------------------------------------------------------------
extern "C" void kernel_launch(void* const* d_in, const int* in_sizes, int n_in,
                              void* d_out, int out_size)
{
    const float* X  = (const float*)d_in[0];
    const float* A  = (const float*)d_in[1];
    const float* Bm = (const float*)d_in[2];
    const float* Cm = (const float*)d_in[3];
    float* Y = (float*)d_out;

    const int sm1 = (4*64*RSH + 4*64) * 4;   // 41984 B
    const int sm3 = (2*64*RSH + 2*64) * 4;   // 20992 B
    cudaFuncSetAttribute(ssd_k1, cudaFuncAttributeMaxDynamicSharedMemorySize, sm1);
    cudaFuncSetAttribute(ssd_k3, cudaFuncAttributeMaxDynamicSharedMemorySize, sm3);

    dim3 grid(HH, CC, BS);
    ssd_k1<<<grid, 128, sm1>>>(X, A, Bm, Cm);
    ssd_k2<<<BS*HH*4, 512>>>(A);
    ssd_k3<<<grid, 128, sm3>>>(A, Cm, Y);
}

// round 13
// speedup vs baseline: 1.6818x; 1.0279x over previous
#include <cuda_runtime.h>
#include <cuda_fp16.h>
#include <cstdint>

#define BS   2
#define SEQ  4096
#define HH   32
#define LLC  64
#define CC   (SEQ/LLC)   // 64
#define RSH  40          // words per half2 table row (32 data + 8 pad)
#define GSTR (HH*64)

__device__ __half g_states[(size_t)BS*CC*HH*64*64];  // [b][c][h][p][n] fp16
__device__ __half g_prefix[(size_t)BS*CC*HH*64*64];  // [b][c][h][p][n] fp16
__device__ __half g_ydiag [(size_t)BS*SEQ*HH*64];    // [b][s][h][p]    fp16

typedef unsigned int u32;

__device__ __forceinline__ u32 f22h(float lo, float hi){
    u32 r; asm("cvt.rn.f16x2.f32 %0, %1, %2;" : "=r"(r) : "f"(hi), "f"(lo)); return r;
}
__device__ __forceinline__ float2 h22f(u32 v){
    __half2 h = *reinterpret_cast<__half2*>(&v);
    return __half22float2(h);
}
// D(16x8,f32) += A(16x16,f16 row) * B(16x8,f16 col)
__device__ __forceinline__ void mma16(float* d, const u32* a, u32 b0, u32 b1){
    asm volatile("mma.sync.aligned.m16n8k16.row.col.f32.f16.f16.f32 "
        "{%0,%1,%2,%3}, {%4,%5,%6,%7}, {%8,%9}, {%0,%1,%2,%3};"
        : "+f"(d[0]), "+f"(d[1]), "+f"(d[2]), "+f"(d[3])
        : "r"(a[0]), "r"(a[1]), "r"(a[2]), "r"(a[3]), "r"(b0), "r"(b1));
}
// skew-paired half2 layout: logical word w (halves 2w,2w+1) of row r at
// physical word r*RSH + 2*((4*(w>>3)+(w&3) + (r>>2))&15) + ((w>>2)&1)
__device__ __forceinline__ int WH(int r, int w){
    return 2*(((4*(w>>3)) + (w&3) + (r>>2)) & 15) + ((w>>2)&1);
}
__device__ __forceinline__ void stpw(u32* t, int r, int w, u32 v){
    t[r*RSH + WH(r,w)] = v;
}
__device__ __forceinline__ uint2 ldpairH(const u32* t, int r, int kk, int qc){
    return *(const uint2*)&t[r*RSH + 2*((4*kk + qc + (r>>2)) & 15)];
}
__device__ __forceinline__ void ldfragH(const u32* t, int r, int kk, int qc, u32* a){
    uint2 lo = ldpairH(t, r, kk, qc), hi = ldpairH(t, r+8, kk, qc);
    a[0] = lo.x; a[1] = hi.x; a[2] = lo.y; a[3] = hi.y;
}

// ===========================================================================
// K1: per (b,c,h). 256 thr / 8 warps; warp tile 16 rows x 32 cols.
// Y_diag (fp16) -> g_ydiag, chunk states (fp16) -> g_states.
// ===========================================================================
__global__ __launch_bounds__(256, 3) void ssd_k1(
    const float* __restrict__ X, const float* __restrict__ A,
    const float* __restrict__ Bm, const float* __restrict__ Cm)
{
    extern __shared__ u32 smw[];
    u32* sXt = smw;                 // [p][s-halves]
    u32* sB  = smw + 64*RSH;        // [s][n-halves]
    u32* sC  = smw + 2*64*RSH;      // [l][n-halves] -> sG [l][s-halves]
    u32* sBt = smw + 3*64*RSH;      // [n][l-halves], dec folded
    float* aA   = (float*)(smw + 4*64*RSH);
    float* el   = aA + 64;
    float* einv = el + 64;
    float* decs = einv + 64;
    u32*   sG   = sC;

    const int h = blockIdx.x, c = blockIdx.y, b = blockIdx.z;
    const int tid = threadIdx.x, wid = tid >> 5, lane = tid & 31;
    const int qr = lane >> 2, qc = lane & 3;
    const int r0 = (wid >> 1) * 16;       // 4 rowgroups of 16
    const int cB = (wid & 1) * 32;        // 2 col halves of 32
    const int base = ((b*SEQ + c*LLC)*HH + h)*64;

    // phase A: load B, C as half2 (paired layout); aA
    #pragma unroll
    for (int i = tid; i < 1024; i += 256) {
        int row = i >> 4, c4 = (i & 15) << 2;
        int g = base + row*GSTR + c4;
        float4 bv = *(const float4*)&Bm[g];
        float4 cv = *(const float4*)&Cm[g];
        stpw(sB, row, c4>>1,     f22h(bv.x, bv.y));
        stpw(sB, row, (c4>>1)+1, f22h(bv.z, bv.w));
        stpw(sC, row, c4>>1,     f22h(cv.x, cv.y));
        stpw(sC, row, (c4>>1)+1, f22h(cv.z, cv.w));
    }
    if (tid < 64) aA[tid] = A[(b*SEQ + c*LLC + tid)*HH + h];

    // phase C: X transposed straight from global into sXt[p][s-halves]
    #pragma unroll
    for (int m = 0; m < 4; m++) {
        int w = wid*4 + m;                        // s-pair
        const float2 x0 = *(const float2*)&X[base + (2*w)*GSTR + 2*lane];
        const float2 x1 = *(const float2*)&X[base + (2*w+1)*GSTR + 2*lane];
        stpw(sXt, 2*lane,   w, f22h(x0.x, x1.x));
        stpw(sXt, 2*lane+1, w, f22h(x0.y, x1.y));
    }
    __syncthreads();

    if (tid < 64) {
        float s = 0.f, mine = 0.f;
        #pragma unroll
        for (int j = 0; j < 64; j++) { s += aA[j]; if (j == tid) mine = s; }
        el[tid]   = __expf(mine);
        einv[tid] = __expf(-mine);
        decs[tid] = __expf(s - mine);
    }
    __syncthreads();

    // phase D: sBt[n][l-halves] = dec[l]*B[l][n]
    #pragma unroll
    for (int m = 0; m < 4; m++) {
        int w = wid*4 + m;                        // l-pair
        float d0 = decs[2*w], d1 = decs[2*w+1];
        u32 v0 = sB[(2*w)*RSH   + WH(2*w,   lane)];
        u32 v1 = sB[(2*w+1)*RSH + WH(2*w+1, lane)];
        float2 fa = h22f(v0), fb = h22f(v1);
        stpw(sBt, 2*lane,   w, f22h(fa.x*d0, fb.x*d1));
        stpw(sBt, 2*lane+1, w, f22h(fa.y*d0, fb.y*d1));
    }

    // ---- mm1: G[l,s] = sum_n C[l,n]*B[s,n] ----
    float g[4][4] = {};
    #pragma unroll
    for (int kk = 0; kk < 4; kk++) {
        u32 a0[4];
        ldfragH(sC, r0+qr, kk, qc, a0);
        #pragma unroll
        for (int t = 0; t < 4; t++) {
            uint2 bb = ldpairH(sB, cB + t*8 + qr, kk, qc);
            mma16(g[t], a0, bb.x, bb.y);
        }
    }
    __syncthreads();   // mm1 reads of sC/sB done (covers phase D too)

    // mask + decay into sG[l][s-halves]
    {
        int l0v = r0 + qr, l1v = l0v + 8;
        float e0 = el[l0v], e1 = el[l1v];
        #pragma unroll
        for (int t = 0; t < 4; t++) {
            int s0 = cB + t*8 + 2*qc, s1 = s0 + 1;
            int w  = ((cB + t*8) >> 1) + qc;
            float i0 = einv[s0], i1 = einv[s1];
            float v0 = (s0 <= l0v) ? g[t][0]*e0*i0 : 0.f;
            float v1 = (s1 <= l0v) ? g[t][1]*e0*i1 : 0.f;
            float v2 = (s0 <= l1v) ? g[t][2]*e1*i0 : 0.f;
            float v3 = (s1 <= l1v) ? g[t][3]*e1*i1 : 0.f;
            stpw(sG, l0v, w, f22h(v0, v1));
            stpw(sG, l1v, w, f22h(v2, v3));
        }
    }
    __syncthreads();

    // ---- mm2: Y[l,p] = sum_s G[l,s]*X[s,p]; store immediately ----
    {
        float y[4][4] = {};
        #pragma unroll
        for (int kk = 0; kk < 4; kk++) {
            u32 a0[4];
            ldfragH(sG, r0+qr, kk, qc, a0);
            #pragma unroll
            for (int t = 0; t < 4; t++) {
                uint2 bb = ldpairH(sXt, cB + t*8 + qr, kk, qc);
                mma16(y[t], a0, bb.x, bb.y);
            }
        }
        int row0 = r0 + qr, row1 = r0 + qr + 8;
        #pragma unroll
        for (int t = 0; t < 4; t++) {
            int c0 = cB + t*8 + 2*qc;
            *(u32*)&g_ydiag[base + row0*GSTR + c0] = f22h(y[t][0], y[t][1]);
            *(u32*)&g_ydiag[base + row1*GSTR + c0] = f22h(y[t][2], y[t][3]);
        }
    }

    // ---- mm3: S[p,n] = sum_l Xt[p,l]*(dec[l]*B[l,n]); store immediately ----
    {
        float st[4][4] = {};
        #pragma unroll
        for (int kk = 0; kk < 4; kk++) {
            u32 a0[4];
            ldfragH(sXt, r0+qr, kk, qc, a0);
            #pragma unroll
            for (int t = 0; t < 4; t++) {
                uint2 bb = ldpairH(sBt, cB + t*8 + qr, kk, qc);
                mma16(st[t], a0, bb.x, bb.y);
            }
        }
        const int sbase = ((b*CC + c)*HH + h)*4096;
        int row0 = r0 + qr, row1 = r0 + qr + 8;
        #pragma unroll
        for (int t = 0; t < 4; t++) {
            int c0 = cB + t*8 + 2*qc;
            *(u32*)&g_states[sbase + row0*64 + c0] = f22h(st[t][0], st[t][1]);
            *(u32*)&g_states[sbase + row1*64 + c0] = f22h(st[t][2], st[t][3]);
        }
    }
}

// ===========================================================================
// K2: inter-chunk scan over fp16 words; fp32 accumulation in registers.
// 256 blocks (4 segments per (b,h)) x 512 threads; prefetched.
// ===========================================================================
__global__ __launch_bounds__(512) void ssd_k2(const float* __restrict__ A)
{
    __shared__ float ea[CC];
    const int blk = blockIdx.x;
    const int seg = blk & 3, bh = blk >> 2, h = bh & 31, b = bh >> 5;
    const int tid = threadIdx.x;

    if (tid < CC) {
        float s = 0.f;
        int ab = (b*SEQ + tid*LLC)*HH + h;
        for (int l = 0; l < LLC; l++) s += A[ab + l*HH];
        ea[tid] = __expf(s);
    }
    __syncthreads();

    const u32* sp = (const u32*)g_states;
    u32* pp = (u32*)g_prefix;
    const int w = seg*512 + tid;                    // word in [0,2048)
    size_t off = ((size_t)(b*CC)*HH + h)*2048 + w;
    float r0 = 0.f, r1 = 0.f;
    u32 v = sp[off];
    for (int z = 0; z < CC; z++) {
        u32 nv = (z+1 < CC) ? sp[off + (size_t)HH*2048] : 0u;
        pp[off] = f22h(r0, r1);
        float2 f = h22f(v);
        float e = ea[z];
        r0 = r0*e + f.x; r1 = r1*e + f.y;
        v = nv;
        off += (size_t)HH*2048;
    }
}

// ===========================================================================
// K3: Y[l,p] = ydiag[l,p] + el[l] * sum_n C[l,n]*St[p,n]  (single fp32 write)
// ===========================================================================
__global__ __launch_bounds__(128) void ssd_k3(
    const float* __restrict__ A, const float* __restrict__ Cm,
    float* __restrict__ Y)
{
    extern __shared__ u32 smw[];
    u32* sC = smw;                 // [l][n-halves]
    u32* sS = smw + 64*RSH;        // [p][n-halves]
    float* aA = (float*)(smw + 2*64*RSH);
    float* el = aA + 64;

    const int h = blockIdx.x, c = blockIdx.y, b = blockIdx.z;
    const int tid = threadIdx.x, wid = tid >> 5, lane = tid & 31;
    const int qr = lane >> 2, qc = lane & 3;
    const int rh = wid >> 1, ch = wid & 1;
    const int rA0 = rh*32, rA1 = rh*32 + 16;
    const int cB = ch*32;
    const int base = ((b*SEQ + c*LLC)*HH + h)*64;
    const int sbase = ((b*CC + c)*HH + h)*4096;

    // C: fp32->fp16 convert; prefix: already half2 words, direct restage
    #pragma unroll
    for (int i = tid; i < 1024; i += 128) {
        int row = i >> 4, c4 = (i & 15) << 2;
        float4 cv = *(const float4*)&Cm[base + row*GSTR + c4];
        stpw(sC, row, c4>>1,     f22h(cv.x, cv.y));
        stpw(sC, row, (c4>>1)+1, f22h(cv.z, cv.w));
        uint2 sv = *(const uint2*)&g_prefix[sbase + row*64 + c4];
        stpw(sS, row, c4>>1,     sv.x);
        stpw(sS, row, (c4>>1)+1, sv.y);
    }
    if (tid < 64) aA[tid] = A[(b*SEQ + c*LLC + tid)*HH + h];
    __syncthreads();
    if (tid < 64) {
        float s = 0.f, mine = 0.f;
        #pragma unroll
        for (int j = 0; j < 64; j++) { s += aA[j]; if (j == tid) mine = s; }
        el[tid] = __expf(mine);
    }
    __syncthreads();

    float y[2][4][4] = {};
    #pragma unroll
    for (int kk = 0; kk < 4; kk++) {
        u32 a0[4], a1[4];
        ldfragH(sC, rA0+qr, kk, qc, a0);
        ldfragH(sC, rA1+qr, kk, qc, a1);
        #pragma unroll
        for (int t = 0; t < 4; t++) {
            uint2 bb = ldpairH(sS, cB + t*8 + qr, kk, qc);
            mma16(y[0][t], a0, bb.x, bb.y);
            mma16(y[1][t], a1, bb.x, bb.y);
        }
    }

    // Y = ydiag + el * acc   (read fp16 stash, single fp32 write)
    #pragma unroll
    for (int mg = 0; mg < 2; mg++) {
        int r0 = rh*32 + mg*16;
        int row0 = r0 + qr, row1 = r0 + qr + 8;
        float e0 = el[row0], e1 = el[row1];
        #pragma unroll
        for (int t = 0; t < 4; t++) {
            int c0 = cB + t*8 + 2*qc;
            float2 d0 = h22f(*(const u32*)&g_ydiag[base + row0*GSTR + c0]);
            float2 d1 = h22f(*(const u32*)&g_ydiag[base + row1*GSTR + c0]);
            *(float2*)&Y[base + row0*GSTR + c0] =
                make_float2(d0.x + e0*y[mg][t][0], d0.y + e0*y[mg][t][1]);
            *(float2*)&Y[base + row1*GSTR + c0] =
                make_float2(d1.x + e1*y[mg][t][2], d1.y + e1*y[mg][t][3]);
        }
    }
}

// ---------------------------------------------------------------------------
extern "C" void kernel_launch(void* const* d_in, const int* in_sizes, int n_in,
                              void* d_out, int out_size)
{
    const float* X  = (const float*)d_in[0];
    const float* A  = (const float*)d_in[1];
    const float* Bm = (const float*)d_in[2];
    const float* Cm = (const float*)d_in[3];
    float* Y = (float*)d_out;

    const int sm1 = (4*64*RSH + 4*64) * 4;   // 41984 B
    const int sm3 = (2*64*RSH + 2*64) * 4;   // 20992 B
    cudaFuncSetAttribute(ssd_k1, cudaFuncAttributeMaxDynamicSharedMemorySize, sm1);
    cudaFuncSetAttribute(ssd_k3, cudaFuncAttributeMaxDynamicSharedMemorySize, sm3);

    dim3 grid(HH, CC, BS);
    ssd_k1<<<grid, 256, sm1>>>(X, A, Bm, Cm);
    ssd_k2<<<BS*HH*4, 512>>>(A);
    ssd_k3<<<grid, 128, sm3>>>(A, Cm, Y);
}